// round 3
// baseline (speedup 1.0000x reference)
#include <cuda_runtime.h>

// Problem constants (fixed by the dataset)
namespace {
constexpr int kB  = 8;
constexpr int kN  = 4096;
constexpr int kE  = 128;   // Din
constexpr int kF  = 256;   // Dout
constexpr int kNT = 32;    // n-tile per block

constexpr int A_S  = 100;  // a_s row stride (floats): 16B-aligned rows, conflict-free reads
constexpr int Y_S  = 100;  // y_s row stride
constexpr int MS_S = 260;  // staged weight-chunk row stride (e-major / c-major)

constexpr int R2_OFF      = kE * A_S;            // 12800 floats
constexpr int SMEM_FLOATS = R2_OFF + kF * Y_S;   // 12800 + 25600 = 38400
constexpr int SMEM_BYTES  = SMEM_FLOATS * 4;     // 153600 B
}

// ---- packed f32x2 helpers (B300 FFMA2 path; ptxas never auto-fuses) ----
__device__ __forceinline__ void ffma2(unsigned long long& d,
                                      unsigned long long a,
                                      unsigned long long b) {
    asm("fma.rn.f32x2 %0, %1, %2, %0;" : "+l"(d) : "l"(a), "l"(b));
}
__device__ __forceinline__ unsigned long long splat2(float v) {
    unsigned long long r;
    asm("mov.b64 %0, {%1, %1};" : "=l"(r) : "f"(v));
    return r;
}
__device__ __forceinline__ float2 unpack2(unsigned long long v) {
    float2 r;
    asm("mov.b64 {%0, %1}, %2;" : "=f"(r.x), "=f"(r.y) : "l"(v));
    return r;
}

__global__ __launch_bounds__(256, 1)
void affine_vn_fused(const float* __restrict__ X, const float* __restrict__ J,
                     const float* __restrict__ Am, const float* __restrict__ Bm,
                     const float* __restrict__ Cm, const float* __restrict__ Wd,
                     float* __restrict__ out)
{
    extern __shared__ float sm[];
    float* a_s = sm;               // [128][A_S]   a-tile; later re-used as W chunk [32][MS_S]
    float* r2  = sm + R2_OFF;      // M chunk [64][MS_S], later y_s [256][Y_S]

    const int t  = threadIdx.x;
    const int b  = blockIdx.y;
    const int n0 = blockIdx.x * kNT;
    const int tx = t & 7;          // 8 m-groups of 12
    const int ty = t >> 3;         // 32 f-groups of 8
    const int fb = ty * 8;
    const int mb = tx * 12;        // 4 points x 3 components

    // ---------------- Phase 1: rotations + projections -> a_s[e][nl*3+i] ----------------
    #pragma unroll 4
    for (int it = 0; it < 16; ++it) {
        const int q  = it * 256 + t;
        const int e  = q & (kE - 1);   // consecutive lanes -> consecutive e (coalesced)
        const int nl = q >> 7;
        const size_t base = (size_t)(b * kN + n0 + nl) * kE + e;
        const float* xp = X + base * 3;
        const float* jp = J + base * 6;   // [3][2] layout: col0 at 0,2,4; col1 at 1,3,5
        const float x0 = xp[0], x1 = xp[1], x2 = xp[2];
        const float u0 = jp[0], u1 = jp[2], u2 = jp[4];
        const float v0 = jp[1], v1 = jp[3], v2 = jp[5];

        const float nn  = u0*u0 + u1*u1 + u2*u2;
        const float iv1 = rsqrtf(fmaxf(nn, 1e-24f));          // == 1/max(||u||,1e-12)
        const float b10 = u0*iv1, b11 = u1*iv1, b12 = u2*iv1;
        const float dp  = b10*v0 + b11*v1 + b12*v2;
        const float w0 = v0 - dp*b10, w1 = v1 - dp*b11, w2 = v2 - dp*b12;
        const float wn  = w0*w0 + w1*w1 + w2*w2;
        const float iv2 = rsqrtf(fmaxf(wn, 1e-24f));
        const float b20 = w0*iv2, b21 = w1*iv2, b22 = w2*iv2;
        const float b30 = b11*b22 - b12*b21;
        const float b31 = b12*b20 - b10*b22;
        const float b32 = b10*b21 - b11*b20;

        float* as = a_s + e * A_S + nl * 3;
        as[0] = x0*b10 + x1*b11 + x2*b12;
        as[1] = x0*b20 + x1*b21 + x2*b22;
        as[2] = x0*b30 + x1*b31 + x2*b32;
    }
    __syncthreads();

    // ---------------- Phase 2: Y = (A+B+C) @ a  (K = 128, chunks of 64) ----------------
    unsigned long long acc2[8][6];
    #pragma unroll
    for (int i = 0; i < 8; ++i)
        #pragma unroll
        for (int j = 0; j < 6; ++j) acc2[i][j] = 0ull;

    for (int kc = 0; kc < kE; kc += 64) {
        // stage Mcomb chunk [64 e][256 f] into r2 (e-major, stride MS_S)
        #pragma unroll 8
        for (int it = 0; it < 64; ++it) {
            const int q  = it * 256 + t;
            const int f  = q >> 6;
            const int el = q & 63;       // consecutive lanes -> consecutive e (coalesced LDG)
            const int gi = f * kE + kc + el;
            r2[el * MS_S + f] = Am[gi] + Bm[gi] + Cm[gi];
        }
        __syncthreads();

        #pragma unroll 4
        for (int el = 0; el < 64; ++el) {
            unsigned long long ms[8];
            {
                const float4 m0 = *reinterpret_cast<const float4*>(r2 + el * MS_S + fb);
                const float4 m1 = *reinterpret_cast<const float4*>(r2 + el * MS_S + fb + 4);
                ms[0]=splat2(m0.x); ms[1]=splat2(m0.y); ms[2]=splat2(m0.z); ms[3]=splat2(m0.w);
                ms[4]=splat2(m1.x); ms[5]=splat2(m1.y); ms[6]=splat2(m1.z); ms[7]=splat2(m1.w);
            }
            unsigned long long av[6];
            {
                const ulonglong2* ap = reinterpret_cast<const ulonglong2*>(a_s + (kc + el) * A_S + mb);
                const ulonglong2 a0 = ap[0], a1 = ap[1], a2 = ap[2];
                av[0]=a0.x; av[1]=a0.y; av[2]=a1.x; av[3]=a1.y; av[4]=a2.x; av[5]=a2.y;
            }
            #pragma unroll
            for (int ff = 0; ff < 8; ++ff)
                #pragma unroll
                for (int j = 0; j < 6; ++j)
                    ffma2(acc2[ff][j], ms[ff], av[j]);
        }
        __syncthreads();   // protect next chunk's overwrite of r2
    }

    // write Y tile into y_s (r2 region; m_s is dead after the sync above)
    // packed pairs are (m, m+1) in order, so store directly as 16B chunks
    #pragma unroll
    for (int ff = 0; ff < 8; ++ff) {
        float* yp = r2 + (fb + ff) * Y_S + mb;
        reinterpret_cast<ulonglong2*>(yp)[0] = make_ulonglong2(acc2[ff][0], acc2[ff][1]);
        reinterpret_cast<ulonglong2*>(yp)[1] = make_ulonglong2(acc2[ff][2], acc2[ff][3]);
        reinterpret_cast<ulonglong2*>(yp)[2] = make_ulonglong2(acc2[ff][4], acc2[ff][5]);
    }
    __syncthreads();

    // ---------------- Phase 3: d = W @ y  (K = 256, chunks of 32; W staged in a_s region) ----
    unsigned long long dcc2[8][6];
    #pragma unroll
    for (int i = 0; i < 8; ++i)
        #pragma unroll
        for (int j = 0; j < 6; ++j) dcc2[i][j] = 0ull;

    for (int kc = 0; kc < kF; kc += 32) {
        #pragma unroll 8
        for (int it = 0; it < 32; ++it) {
            const int q  = it * 256 + t;
            const int o  = q >> 5;
            const int cl = q & 31;       // consecutive lanes -> consecutive c (coalesced LDG)
            a_s[cl * MS_S + o] = Wd[o * kF + kc + cl];
        }
        __syncthreads();

        #pragma unroll 4
        for (int cl = 0; cl < 32; ++cl) {
            unsigned long long ws[8];
            {
                const float4 w0 = *reinterpret_cast<const float4*>(a_s + cl * MS_S + fb);
                const float4 w1 = *reinterpret_cast<const float4*>(a_s + cl * MS_S + fb + 4);
                ws[0]=splat2(w0.x); ws[1]=splat2(w0.y); ws[2]=splat2(w0.z); ws[3]=splat2(w0.w);
                ws[4]=splat2(w1.x); ws[5]=splat2(w1.y); ws[6]=splat2(w1.z); ws[7]=splat2(w1.w);
            }
            unsigned long long yv[6];
            {
                const ulonglong2* yp = reinterpret_cast<const ulonglong2*>(r2 + (kc + cl) * Y_S + mb);
                const ulonglong2 y0 = yp[0], y1 = yp[1], y2 = yp[2];
                yv[0]=y0.x; yv[1]=y0.y; yv[2]=y1.x; yv[3]=y1.y; yv[4]=y2.x; yv[5]=y2.y;
            }
            #pragma unroll
            for (int ff = 0; ff < 8; ++ff)
                #pragma unroll
                for (int j = 0; j < 6; ++j)
                    ffma2(dcc2[ff][j], ws[ff], yv[j]);
        }
        __syncthreads();
    }

    // ---------------- Epilogue: VN-LeakyReLU + store [B, F, 3, N] ----------------
    #pragma unroll
    for (int ff = 0; ff < 8; ++ff) {
        const int o = fb + ff;
        float xv[12];
        {
            const float* yp = r2 + o * Y_S + mb;
            const float4 y0 = *reinterpret_cast<const float4*>(yp);
            const float4 y1 = *reinterpret_cast<const float4*>(yp + 4);
            const float4 y2 = *reinterpret_cast<const float4*>(yp + 8);
            xv[0]=y0.x; xv[1]=y0.y; xv[2]=y0.z;  xv[3]=y0.w;
            xv[4]=y1.x; xv[5]=y1.y; xv[6]=y1.z;  xv[7]=y1.w;
            xv[8]=y2.x; xv[9]=y2.y; xv[10]=y2.z; xv[11]=y2.w;
        }
        float dv[12];
        #pragma unroll
        for (int j = 0; j < 6; ++j) {
            const float2 p = unpack2(dcc2[ff][j]);
            dv[2*j]   = p.x;
            dv[2*j+1] = p.y;
        }
        float res[12];
        #pragma unroll
        for (int nq = 0; nq < 4; ++nq) {
            const float X0 = xv[nq*3+0], X1 = xv[nq*3+1], X2 = xv[nq*3+2];
            const float D0 = dv[nq*3+0], D1 = dv[nq*3+1], D2 = dv[nq*3+2];
            const float dot = X0*D0 + X1*D1 + X2*D2;
            const float dsq = D0*D0 + D1*D1 + D2*D2;
            // out = x                         if dot >= 0
            //     = x - 0.8*dot/(dsq+eps)*d   if dot <  0
            const float s = (dot >= 0.0f) ? 0.0f : 0.8f * dot * __fdividef(1.0f, dsq + 1e-6f);
            res[nq*3+0] = X0 - s * D0;
            res[nq*3+1] = X1 - s * D1;
            res[nq*3+2] = X2 - s * D2;
        }
        const size_t ob = ((size_t)(b * kF + o) * 3) * kN + n0 + tx * 4;
        #pragma unroll
        for (int i = 0; i < 3; ++i) {
            const float4 v = make_float4(res[0+i], res[3+i], res[6+i], res[9+i]);
            *reinterpret_cast<float4*>(out + ob + (size_t)i * kN) = v;
        }
    }
}

extern "C" void kernel_launch(void* const* d_in, const int* in_sizes, int n_in,
                              void* d_out, int out_size) {
    (void)in_sizes; (void)n_in; (void)out_size;
    const float* X  = (const float*)d_in[0];
    const float* J  = (const float*)d_in[1];
    const float* Am = (const float*)d_in[2];
    const float* Bm = (const float*)d_in[3];
    const float* Cm = (const float*)d_in[4];
    const float* Wd = (const float*)d_in[5];
    // d_in[6] = "device" scalar, unused
    float* out = (float*)d_out;

    cudaFuncSetAttribute(affine_vn_fused,
                         cudaFuncAttributeMaxDynamicSharedMemorySize, SMEM_BYTES);
    dim3 grid(kN / kNT, kB);
    affine_vn_fused<<<grid, 256, SMEM_BYTES>>>(X, J, Am, Bm, Cm, Wd, out);
}

// round 4
// speedup vs baseline: 2.2292x; 2.2292x over previous
#include <cuda_runtime.h>

// Problem constants (fixed by the dataset)
namespace {
constexpr int kB  = 8;
constexpr int kN  = 4096;
constexpr int kE  = 128;   // Din
constexpr int kF  = 256;   // Dout
constexpr int kNT = 32;    // n-tile per block

constexpr int A_S  = 100;  // a_s row stride (floats): 16B-aligned rows, conflict-free reads
constexpr int Y_S  = 100;  // y_s row stride
constexpr int MS_S = 260;  // staged weight-chunk row stride (e-major)

constexpr int W_OFF = kE * A_S;          // 12800  (w_s chunk region, 64 x MS_S)
constexpr int Y_OFF = W_OFF + 64 * MS_S; // 29440  (y_s region, 256 x Y_S)
constexpr int SMEM_FLOATS = Y_OFF + kF * Y_S;  // 55040
constexpr int SMEM_BYTES  = SMEM_FLOATS * 4;   // 220160 B
}

// Precomputed per-launch weights (device globals: no allocation allowed)
__device__ float g_Mc[kF * kE];  // Mc = A + B + C                [f][e]
__device__ float g_W2[kF * kE];  // W2 = W @ Mc  (folded GEMM2)   [o][e]

// ---- prep kernel 1: Mc = A + B + C ----
__global__ void prep_mc(const float* __restrict__ Am, const float* __restrict__ Bm,
                        const float* __restrict__ Cm) {
    const int i = blockIdx.x * 256 + threadIdx.x;
    g_Mc[i] = Am[i] + Bm[i] + Cm[i];
}

// ---- prep kernel 2: W2[o][e] = sum_c W[o][c] * Mc[c][e] ----
__global__ __launch_bounds__(128)
void prep_w2(const float* __restrict__ Wd) {
    __shared__ float wrow[kF];
    const int o = blockIdx.x;
    const int e = threadIdx.x;  // 128 threads, consecutive e -> coalesced Mc loads
    for (int c = threadIdx.x; c < kF; c += 128) wrow[c] = Wd[o * kF + c];
    __syncthreads();
    float acc = 0.0f;
    #pragma unroll 8
    for (int c = 0; c < kF; ++c)
        acc = fmaf(wrow[c], g_Mc[c * kE + e], acc);
    g_W2[o * kE + e] = acc;
}

__global__ __launch_bounds__(256, 1)
void affine_vn_fused(const float* __restrict__ X, const float* __restrict__ J,
                     float* __restrict__ out)
{
    extern __shared__ float sm[];
    float* a_s = sm;            // [128][A_S]  rotated-projection tile
    float* w_s = sm + W_OFF;    // [64][MS_S]  staged weight chunk (e-major)
    float* y_s = sm + Y_OFF;    // [256][Y_S]  x-tile (Y), thread-private round trip

    const int t  = threadIdx.x;
    const int b  = blockIdx.y;
    const int n0 = blockIdx.x * kNT;
    const int tx = t & 7;       // 8 m-groups of 12
    const int ty = t >> 3;      // 32 f-groups of 8
    const int fb = ty * 8;
    const int mb = tx * 12;     // 4 points x 3 components

    // ---------------- Phase 1: rotations + projections -> a_s[e][nl*3+i] ----------------
    #pragma unroll 4
    for (int it = 0; it < 16; ++it) {
        const int q  = it * 256 + t;
        const int e  = q & (kE - 1);   // consecutive lanes -> consecutive e (coalesced)
        const int nl = q >> 7;
        const size_t base = (size_t)(b * kN + n0 + nl) * kE + e;
        const float* xp = X + base * 3;
        const float* jp = J + base * 6;   // [3][2] layout: col0 at 0,2,4; col1 at 1,3,5
        const float x0 = xp[0], x1 = xp[1], x2 = xp[2];
        const float u0 = jp[0], u1 = jp[2], u2 = jp[4];
        const float v0 = jp[1], v1 = jp[3], v2 = jp[5];

        const float nn  = u0*u0 + u1*u1 + u2*u2;
        const float iv1 = rsqrtf(fmaxf(nn, 1e-24f));          // == 1/max(||u||,1e-12)
        const float b10 = u0*iv1, b11 = u1*iv1, b12 = u2*iv1;
        const float dp  = b10*v0 + b11*v1 + b12*v2;
        const float w0 = v0 - dp*b10, w1 = v1 - dp*b11, w2 = v2 - dp*b12;
        const float wn  = w0*w0 + w1*w1 + w2*w2;
        const float iv2 = rsqrtf(fmaxf(wn, 1e-24f));
        const float b20 = w0*iv2, b21 = w1*iv2, b22 = w2*iv2;
        const float b30 = b11*b22 - b12*b21;
        const float b31 = b12*b20 - b10*b22;
        const float b32 = b10*b21 - b11*b20;

        float* as = a_s + e * A_S + nl * 3;
        as[0] = x0*b10 + x1*b11 + x2*b12;
        as[1] = x0*b20 + x1*b21 + x2*b22;
        as[2] = x0*b30 + x1*b31 + x2*b32;
    }
    __syncthreads();

    // ---------------- Phase 2: x = Mc @ a  (K = 128, chunks of 64) ----------------
    {
        float acc[8][12];
        #pragma unroll
        for (int i = 0; i < 8; ++i)
            #pragma unroll
            for (int j = 0; j < 12; ++j) acc[i][j] = 0.0f;

        for (int kc = 0; kc < kE; kc += 64) {
            // stage Mc chunk [64 e][256 f] into w_s (e-major, stride MS_S)
            #pragma unroll 8
            for (int it = 0; it < 64; ++it) {
                const int q  = it * 256 + t;
                const int f  = q >> 6;
                const int el = q & 63;   // consecutive lanes -> consecutive e (coalesced LDG)
                w_s[el * MS_S + f] = g_Mc[f * kE + kc + el];
            }
            __syncthreads();

            #pragma unroll 4
            for (int el = 0; el < 64; ++el) {
                float mv[8];
                {
                    const float4 m0 = *reinterpret_cast<const float4*>(w_s + el * MS_S + fb);
                    const float4 m1 = *reinterpret_cast<const float4*>(w_s + el * MS_S + fb + 4);
                    mv[0]=m0.x; mv[1]=m0.y; mv[2]=m0.z; mv[3]=m0.w;
                    mv[4]=m1.x; mv[5]=m1.y; mv[6]=m1.z; mv[7]=m1.w;
                }
                float av[12];
                {
                    const float* ap = a_s + (kc + el) * A_S + mb;
                    const float4 a0 = *reinterpret_cast<const float4*>(ap);
                    const float4 a1 = *reinterpret_cast<const float4*>(ap + 4);
                    const float4 a2 = *reinterpret_cast<const float4*>(ap + 8);
                    av[0]=a0.x; av[1]=a0.y; av[2]=a0.z;  av[3]=a0.w;
                    av[4]=a1.x; av[5]=a1.y; av[6]=a1.z;  av[7]=a1.w;
                    av[8]=a2.x; av[9]=a2.y; av[10]=a2.z; av[11]=a2.w;
                }
                #pragma unroll
                for (int ff = 0; ff < 8; ++ff)
                    #pragma unroll
                    for (int mm = 0; mm < 12; ++mm)
                        acc[ff][mm] = fmaf(mv[ff], av[mm], acc[ff][mm]);
            }
            __syncthreads();   // protect next chunk's overwrite of w_s
        }

        // spill x-tile to y_s (thread-private mapping: written & read by same thread)
        #pragma unroll
        for (int ff = 0; ff < 8; ++ff) {
            float* yp = y_s + (fb + ff) * Y_S + mb;
            *reinterpret_cast<float4*>(yp)     = make_float4(acc[ff][0], acc[ff][1], acc[ff][2],  acc[ff][3]);
            *reinterpret_cast<float4*>(yp + 4) = make_float4(acc[ff][4], acc[ff][5], acc[ff][6],  acc[ff][7]);
            *reinterpret_cast<float4*>(yp + 8) = make_float4(acc[ff][8], acc[ff][9], acc[ff][10], acc[ff][11]);
        }
    }

    // ---------------- Phase 3: d = W2 @ a  (K = 128, chunks of 64; same a_s!) ----------
    float dcc[8][12];
    #pragma unroll
    for (int i = 0; i < 8; ++i)
        #pragma unroll
        for (int j = 0; j < 12; ++j) dcc[i][j] = 0.0f;

    for (int kc = 0; kc < kE; kc += 64) {
        #pragma unroll 8
        for (int it = 0; it < 64; ++it) {
            const int q  = it * 256 + t;
            const int f  = q >> 6;
            const int el = q & 63;
            w_s[el * MS_S + f] = g_W2[f * kE + kc + el];
        }
        __syncthreads();

        #pragma unroll 4
        for (int el = 0; el < 64; ++el) {
            float wv[8];
            {
                const float4 w0 = *reinterpret_cast<const float4*>(w_s + el * MS_S + fb);
                const float4 w1 = *reinterpret_cast<const float4*>(w_s + el * MS_S + fb + 4);
                wv[0]=w0.x; wv[1]=w0.y; wv[2]=w0.z; wv[3]=w0.w;
                wv[4]=w1.x; wv[5]=w1.y; wv[6]=w1.z; wv[7]=w1.w;
            }
            float av[12];
            {
                const float* ap = a_s + (kc + el) * A_S + mb;
                const float4 a0 = *reinterpret_cast<const float4*>(ap);
                const float4 a1 = *reinterpret_cast<const float4*>(ap + 4);
                const float4 a2 = *reinterpret_cast<const float4*>(ap + 8);
                av[0]=a0.x; av[1]=a0.y; av[2]=a0.z;  av[3]=a0.w;
                av[4]=a1.x; av[5]=a1.y; av[6]=a1.z;  av[7]=a1.w;
                av[8]=a2.x; av[9]=a2.y; av[10]=a2.z; av[11]=a2.w;
            }
            #pragma unroll
            for (int ff = 0; ff < 8; ++ff)
                #pragma unroll
                for (int mm = 0; mm < 12; ++mm)
                    dcc[ff][mm] = fmaf(wv[ff], av[mm], dcc[ff][mm]);
        }
        if (kc == 0) __syncthreads();   // protect second chunk's overwrite of w_s
    }

    // ---------------- Epilogue: VN-LeakyReLU + store [B, F, 3, N] ----------------
    #pragma unroll
    for (int ff = 0; ff < 8; ++ff) {
        const int o = fb + ff;
        float xv[12];
        {
            const float* yp = y_s + o * Y_S + mb;  // thread-private: no sync needed
            const float4 y0 = *reinterpret_cast<const float4*>(yp);
            const float4 y1 = *reinterpret_cast<const float4*>(yp + 4);
            const float4 y2 = *reinterpret_cast<const float4*>(yp + 8);
            xv[0]=y0.x; xv[1]=y0.y; xv[2]=y0.z;  xv[3]=y0.w;
            xv[4]=y1.x; xv[5]=y1.y; xv[6]=y1.z;  xv[7]=y1.w;
            xv[8]=y2.x; xv[9]=y2.y; xv[10]=y2.z; xv[11]=y2.w;
        }
        float res[12];
        #pragma unroll
        for (int nq = 0; nq < 4; ++nq) {
            const float X0 = xv[nq*3+0], X1 = xv[nq*3+1], X2 = xv[nq*3+2];
            const float D0 = dcc[ff][nq*3+0], D1 = dcc[ff][nq*3+1], D2 = dcc[ff][nq*3+2];
            const float dot = X0*D0 + X1*D1 + X2*D2;
            const float dsq = D0*D0 + D1*D1 + D2*D2;
            // out = x                         if dot >= 0
            //     = x - 0.8*dot/(dsq+eps)*d   if dot <  0
            const float s = (dot >= 0.0f) ? 0.0f : 0.8f * dot * __fdividef(1.0f, dsq + 1e-6f);
            res[nq*3+0] = X0 - s * D0;
            res[nq*3+1] = X1 - s * D1;
            res[nq*3+2] = X2 - s * D2;
        }
        const size_t ob = ((size_t)(b * kF + o) * 3) * kN + n0 + tx * 4;
        #pragma unroll
        for (int i = 0; i < 3; ++i) {
            const float4 v = make_float4(res[0+i], res[3+i], res[6+i], res[9+i]);
            *reinterpret_cast<float4*>(out + ob + (size_t)i * kN) = v;
        }
    }
}

extern "C" void kernel_launch(void* const* d_in, const int* in_sizes, int n_in,
                              void* d_out, int out_size) {
    (void)in_sizes; (void)n_in; (void)out_size;
    const float* X  = (const float*)d_in[0];
    const float* J  = (const float*)d_in[1];
    const float* Am = (const float*)d_in[2];
    const float* Bm = (const float*)d_in[3];
    const float* Cm = (const float*)d_in[4];
    const float* Wd = (const float*)d_in[5];
    // d_in[6] = "device" scalar, unused
    float* out = (float*)d_out;

    // Fold the weights once per launch: Mc = A+B+C, W2 = W @ Mc
    prep_mc<<<(kF * kE) / 256, 256>>>(Am, Bm, Cm);
    prep_w2<<<kF, 128>>>(Wd);

    cudaFuncSetAttribute(affine_vn_fused,
                         cudaFuncAttributeMaxDynamicSharedMemorySize, SMEM_BYTES);
    dim3 grid(kN / kNT, kB);
    affine_vn_fused<<<grid, 256, SMEM_BYTES>>>(X, J, out);
}

// round 7
// speedup vs baseline: 4.1836x; 1.8768x over previous
#include <cuda_runtime.h>
#include <cuda_bf16.h>
#include <cstdint>

// ---------------------------------------------------------------------------
// Problem constants
// ---------------------------------------------------------------------------
namespace {
constexpr int kB   = 8;
constexpr int kN   = 4096;
constexpr int kE   = 128;   // Din  (GEMM K)
constexpr int kF   = 256;   // Dout (GEMM M)
constexpr int kPTS = 32;    // points per block
constexpr int kM   = 3 * kPTS;  // 96 = GEMM N

// smem layout (bytes)
constexpr int AT_STRIDE = 272;                  // a-tile row stride bytes (136 bf16), 272%128==16
constexpr int OFF_AH    = 0;                    // a hi [96][136] bf16  -> 26112 B
constexpr int OFF_AL    = 26112;                // a lo                 -> 26112 B
constexpr int W_STRIDE  = 144;                  // weight chunk row stride bytes (72 bf16), 144%128==16
constexpr int OFF_WH    = 52224;                // W chunk hi [256][72] -> 36864 B
constexpr int OFF_WL    = OFF_WH + 36864;       // W chunk lo           -> 36864 B
constexpr int RES_S     = 100;                  // result region row stride (floats)
constexpr int OFF_RX    = OFF_WL + 36864;       // x region [256][100] f32 = 102400 B
constexpr int OFF_RD    = 0;                    // d region overlays dead a/w tiles (102400 <= 125952)
constexpr int SMEM_BYTES = OFF_RX + kF * RES_S * 4;   // 228352 B
}

// ---------------------------------------------------------------------------
// Per-launch folded weights (device globals — no allocation allowed)
// ---------------------------------------------------------------------------
__device__ float g_Mc[kF * kE];   // Mc = A + B + C       [f][e]
__device__ float g_W2[kF * kE];   // W2 = W @ Mc          [f][e]
__device__ __align__(16) __nv_bfloat16 g_McHi[kF * kE];
__device__ __align__(16) __nv_bfloat16 g_McLo[kF * kE];
__device__ __align__(16) __nv_bfloat16 g_W2Hi[kF * kE];
__device__ __align__(16) __nv_bfloat16 g_W2Lo[kF * kE];

// ---------------------------------------------------------------------------
// Prep kernels
// ---------------------------------------------------------------------------
__global__ void prep_mc(const float* __restrict__ Am, const float* __restrict__ Bm,
                        const float* __restrict__ Cm) {
    const int i = blockIdx.x * 256 + threadIdx.x;
    g_Mc[i] = Am[i] + Bm[i] + Cm[i];
}

__global__ __launch_bounds__(128)
void prep_w2(const float* __restrict__ Wd) {
    __shared__ float wrow[kF];
    const int o = blockIdx.x;
    const int e = threadIdx.x;
    for (int c = threadIdx.x; c < kF; c += 128) wrow[c] = Wd[o * kF + c];
    __syncthreads();
    float acc = 0.0f;
    #pragma unroll 8
    for (int c = 0; c < kF; ++c)
        acc = fmaf(wrow[c], g_Mc[c * kE + e], acc);
    g_W2[o * kE + e] = acc;
}

__global__ void prep_split() {
    const int i = blockIdx.x * 256 + threadIdx.x;
    {
        const float v = g_Mc[i];
        const __nv_bfloat16 hi = __float2bfloat16(v);
        g_McHi[i] = hi;
        g_McLo[i] = __float2bfloat16(v - __bfloat162float(hi));
    }
    {
        const float v = g_W2[i];
        const __nv_bfloat16 hi = __float2bfloat16(v);
        g_W2Hi[i] = hi;
        g_W2Lo[i] = __float2bfloat16(v - __bfloat162float(hi));
    }
}

// ---------------------------------------------------------------------------
// mma.sync m16n8k16 bf16 (sm_80 baseline — compiles under compute_103)
// ---------------------------------------------------------------------------
__device__ __forceinline__ void mma16816(float (&c)[4], const uint32_t (&a)[4],
                                         const uint32_t (&b)[2]) {
    asm volatile(
        "mma.sync.aligned.m16n8k16.row.col.f32.bf16.bf16.f32 "
        "{%0,%1,%2,%3}, {%4,%5,%6,%7}, {%8,%9}, {%0,%1,%2,%3};"
        : "+f"(c[0]), "+f"(c[1]), "+f"(c[2]), "+f"(c[3])
        : "r"(a[0]), "r"(a[1]), "r"(a[2]), "r"(a[3]), "r"(b[0]), "r"(b[1]));
}

// ---------------------------------------------------------------------------
// One GEMM phase: acc[2][12][4] += weight(hi/lo) [f0w..f0w+32][0..128] x a-tile
// 3-pass split: Whi*ahi + Whi*alo + Wlo*ahi
// ---------------------------------------------------------------------------
__device__ __forceinline__ void gemm_phase(char* smem,
                                           const __nv_bfloat16* __restrict__ ghi,
                                           const __nv_bfloat16* __restrict__ glo,
                                           float (&acc)[2][12][4],
                                           int t, int wid, int lane) {
    const int f0w  = wid * 32;
    const int arow = lane >> 2;        // 0..7
    const int acol = (lane & 3) * 2;   // 0,2,4,6

    #pragma unroll 1
    for (int ck = 0; ck < 2; ++ck) {
        // ---- stage weight chunk [256 f][64 e] hi+lo ----
        #pragma unroll 8
        for (int it = 0; it < 8; ++it) {
            const int q = it * 256 + t;          // 0..2047
            const int f = q >> 3, j = q & 7;
            const size_t gi = (size_t)f * kE + ck * 64 + j * 8;
            *reinterpret_cast<uint4*>(smem + OFF_WH + f * W_STRIDE + j * 16) =
                *reinterpret_cast<const uint4*>(ghi + gi);
            *reinterpret_cast<uint4*>(smem + OFF_WL + f * W_STRIDE + j * 16) =
                *reinterpret_cast<const uint4*>(glo + gi);
        }
        __syncthreads();

        #pragma unroll
        for (int kk = 0; kk < 4; ++kk) {
            const int keg = ck * 64 + kk * 16;   // global e base (a-tile holds full 128)

            // ---- B fragments (a-tile hi/lo), explicit per-lane LDS.32 ----
            uint32_t bh[12][2], bl[12][2];
            #pragma unroll
            for (int n = 0; n < 12; ++n) {
                const int ba = (n * 8 + arow) * AT_STRIDE + (keg + acol) * 2;
                bh[n][0] = *reinterpret_cast<const uint32_t*>(smem + OFF_AH + ba);
                bh[n][1] = *reinterpret_cast<const uint32_t*>(smem + OFF_AH + ba + 16);
                bl[n][0] = *reinterpret_cast<const uint32_t*>(smem + OFF_AL + ba);
                bl[n][1] = *reinterpret_cast<const uint32_t*>(smem + OFF_AL + ba + 16);
            }

            #pragma unroll
            for (int tf = 0; tf < 2; ++tf) {
                const int wa = (f0w + tf * 16 + arow) * W_STRIDE + (kk * 16 + acol) * 2;
                uint32_t ah[4], al[4];
                ah[0] = *reinterpret_cast<const uint32_t*>(smem + OFF_WH + wa);
                ah[1] = *reinterpret_cast<const uint32_t*>(smem + OFF_WH + wa + 8 * W_STRIDE);
                ah[2] = *reinterpret_cast<const uint32_t*>(smem + OFF_WH + wa + 16);
                ah[3] = *reinterpret_cast<const uint32_t*>(smem + OFF_WH + wa + 8 * W_STRIDE + 16);
                al[0] = *reinterpret_cast<const uint32_t*>(smem + OFF_WL + wa);
                al[1] = *reinterpret_cast<const uint32_t*>(smem + OFF_WL + wa + 8 * W_STRIDE);
                al[2] = *reinterpret_cast<const uint32_t*>(smem + OFF_WL + wa + 16);
                al[3] = *reinterpret_cast<const uint32_t*>(smem + OFF_WL + wa + 8 * W_STRIDE + 16);

                #pragma unroll
                for (int n = 0; n < 12; ++n) mma16816(acc[tf][n], ah, bh[n]);  // hi*hi
                #pragma unroll
                for (int n = 0; n < 12; ++n) mma16816(acc[tf][n], ah, bl[n]);  // hi*lo
                #pragma unroll
                for (int n = 0; n < 12; ++n) mma16816(acc[tf][n], al, bh[n]);  // lo*hi
            }
        }
        __syncthreads();   // protect restage / region reuse
    }
}

// scatter D-fragment accumulators into res[f][m] (stride RES_S floats)
__device__ __forceinline__ void scatter_acc(char* smem, int res_off,
                                            const float (&acc)[2][12][4],
                                            int wid, int lane) {
    const int f0w  = wid * 32;
    const int arow = lane >> 2;
    const int acol = (lane & 3) * 2;
    float* res = reinterpret_cast<float*>(smem + res_off);
    #pragma unroll
    for (int tf = 0; tf < 2; ++tf) {
        const int f = f0w + tf * 16 + arow;
        #pragma unroll
        for (int n = 0; n < 12; ++n) {
            const int m = n * 8 + acol;
            *reinterpret_cast<float2*>(res + f * RES_S + m) =
                make_float2(acc[tf][n][0], acc[tf][n][1]);
            *reinterpret_cast<float2*>(res + (f + 8) * RES_S + m) =
                make_float2(acc[tf][n][2], acc[tf][n][3]);
        }
    }
}

// ---------------------------------------------------------------------------
// Main fused kernel
// ---------------------------------------------------------------------------
__global__ __launch_bounds__(256, 1)
void affine_vn_mma(const float* __restrict__ X, const float* __restrict__ J,
                   float* __restrict__ out)
{
    extern __shared__ char smem[];
    const int t    = threadIdx.x;
    const int wid  = t >> 5;
    const int lane = t & 31;
    const int b    = blockIdx.y;
    const int n0   = blockIdx.x * kPTS;

    // ---- Phase 1: rotations + projections -> a-tile bf16 hi/lo [m][e] ----
    #pragma unroll 4
    for (int it = 0; it < 16; ++it) {
        const int q  = it * 256 + t;
        const int e  = q & (kE - 1);
        const int nl = q >> 7;
        const size_t base = (size_t)(b * kN + n0 + nl) * kE + e;
        const float* xp = X + base * 3;
        const float* jp = J + base * 6;
        const float x0 = xp[0], x1 = xp[1], x2 = xp[2];
        const float u0 = jp[0], u1 = jp[2], u2 = jp[4];
        const float v0 = jp[1], v1 = jp[3], v2 = jp[5];

        const float nn  = u0*u0 + u1*u1 + u2*u2;
        const float iv1 = rsqrtf(fmaxf(nn, 1e-24f));
        const float b10 = u0*iv1, b11 = u1*iv1, b12 = u2*iv1;
        const float dp  = b10*v0 + b11*v1 + b12*v2;
        const float w0 = v0 - dp*b10, w1 = v1 - dp*b11, w2 = v2 - dp*b12;
        const float wn  = w0*w0 + w1*w1 + w2*w2;
        const float iv2 = rsqrtf(fmaxf(wn, 1e-24f));
        const float b20 = w0*iv2, b21 = w1*iv2, b22 = w2*iv2;
        const float b30 = b11*b22 - b12*b21;
        const float b31 = b12*b20 - b10*b22;
        const float b32 = b10*b21 - b11*b20;

        float av[3];
        av[0] = x0*b10 + x1*b11 + x2*b12;
        av[1] = x0*b20 + x1*b21 + x2*b22;
        av[2] = x0*b30 + x1*b31 + x2*b32;

        #pragma unroll
        for (int i = 0; i < 3; ++i) {
            const int m = nl * 3 + i;
            const int off = m * AT_STRIDE + e * 2;
            const float v = av[i];
            const __nv_bfloat16 hi = __float2bfloat16(v);
            const __nv_bfloat16 lo = __float2bfloat16(v - __bfloat162float(hi));
            *reinterpret_cast<__nv_bfloat16*>(smem + OFF_AH + off) = hi;
            *reinterpret_cast<__nv_bfloat16*>(smem + OFF_AL + off) = lo;
        }
    }
    __syncthreads();

    // ---- Phase 2: x = Mc (x) a ----
    {
        float accx[2][12][4];
        #pragma unroll
        for (int i = 0; i < 2; ++i)
            #pragma unroll
            for (int j = 0; j < 12; ++j)
                #pragma unroll
                for (int k = 0; k < 4; ++k) accx[i][j][k] = 0.0f;
        gemm_phase(smem, g_McHi, g_McLo, accx, t, wid, lane);
        scatter_acc(smem, OFF_RX, accx, wid, lane);   // x region is dedicated, no race
    }

    // ---- Phase 3: d = W2 (x) a ----
    {
        float accd[2][12][4];
        #pragma unroll
        for (int i = 0; i < 2; ++i)
            #pragma unroll
            for (int j = 0; j < 12; ++j)
                #pragma unroll
                for (int k = 0; k < 4; ++k) accd[i][j][k] = 0.0f;
        gemm_phase(smem, g_W2Hi, g_W2Lo, accd, t, wid, lane);
        // a/w tiles dead now (gemm_phase ends with __syncthreads) -> overlay d at offset 0
        scatter_acc(smem, OFF_RD, accd, wid, lane);
    }
    __syncthreads();

    // ---- Epilogue: VN-LeakyReLU on (x,d) triples + coalesced store [B,F,3,N] ----
    {
        const float* xs_base = reinterpret_cast<const float*>(smem + OFF_RX);
        const float* ds_base = reinterpret_cast<const float*>(smem + OFF_RD);
        #pragma unroll 4
        for (int r = 0; r < 32; ++r) {
            const int f = wid * 32 + r;
            const float* xs = xs_base + f * RES_S + 3 * lane;  // stride-3: conflict-free
            const float* ds = ds_base + f * RES_S + 3 * lane;
            const float X0 = xs[0], X1 = xs[1], X2 = xs[2];
            const float D0 = ds[0], D1 = ds[1], D2 = ds[2];
            const float dot = X0*D0 + X1*D1 + X2*D2;
            const float dsq = D0*D0 + D1*D1 + D2*D2;
            const float s = (dot >= 0.0f) ? 0.0f : 0.8f * dot * __fdividef(1.0f, dsq + 1e-6f);
            const size_t ob = ((size_t)(b * kF + f) * 3) * kN + n0 + lane;
            out[ob]             = X0 - s * D0;
            out[ob + kN]        = X1 - s * D1;
            out[ob + 2 * (size_t)kN] = X2 - s * D2;
        }
    }
}

// ---------------------------------------------------------------------------
// Launcher
// ---------------------------------------------------------------------------
extern "C" void kernel_launch(void* const* d_in, const int* in_sizes, int n_in,
                              void* d_out, int out_size) {
    (void)in_sizes; (void)n_in; (void)out_size;
    const float* X  = (const float*)d_in[0];
    const float* J  = (const float*)d_in[1];
    const float* Am = (const float*)d_in[2];
    const float* Bm = (const float*)d_in[3];
    const float* Cm = (const float*)d_in[4];
    const float* Wd = (const float*)d_in[5];
    float* out = (float*)d_out;

    prep_mc<<<(kF * kE) / 256, 256>>>(Am, Bm, Cm);
    prep_w2<<<kF, 128>>>(Wd);
    prep_split<<<(kF * kE) / 256, 256>>>();

    cudaFuncSetAttribute(affine_vn_mma,
                         cudaFuncAttributeMaxDynamicSharedMemorySize, SMEM_BYTES);
    dim3 grid(kN / kPTS, kB);
    affine_vn_mma<<<grid, 256, SMEM_BYTES>>>(X, J, out);
}